// round 7
// baseline (speedup 1.0000x reference)
#include <cuda_runtime.h>

#define HH 128
#define WW 128
#define HW (HH * WW)
#define BB 4

typedef unsigned long long ull;
typedef unsigned int u32;

__device__ __forceinline__ ull pack2(float lo, float hi) {
    ull r; asm("mov.b64 %0,{%1,%2};" : "=l"(r) : "f"(lo), "f"(hi)); return r;
}
__device__ __forceinline__ float2 unpack2(ull v) {
    float2 r; asm("mov.b64 {%0,%1},%2;" : "=f"(r.x), "=f"(r.y) : "l"(v)); return r;
}
// d = a*b + d  (two independent fp32 FMAs per instruction)
__device__ __forceinline__ void fma2(ull& d, ull a, ull b) {
    asm("fma.rn.f32x2 %0,%1,%2,%0;" : "+l"(d) : "l"(a), "l"(b));
}
// async 4B copy, zero-fill when sz==0
__device__ __forceinline__ void cp_async4(u32 dst, const float* src, int sz) {
    asm volatile("cp.async.ca.shared.global [%0], [%1], 4, %2;"
                 :: "r"(dst), "l"(src), "r"(sz));
}
__device__ __forceinline__ void cp_async16(u32 dst, const void* src) {
    asm volatile("cp.async.cg.shared.global [%0], [%1], 16;"
                 :: "r"(dst), "l"(src));
}
__device__ __forceinline__ void cp_commit() {
    asm volatile("cp.async.commit_group;");
}
__device__ __forceinline__ void cp_wait1() {
    asm volatile("cp.async.wait_group 1;");
}

// Scratch (allocation-free rule: __device__ globals)
__device__ float g_buf1[(size_t)BB * 64 * HW];   // offset_1
__device__ float g_buf2[(size_t)BB * 64 * HW];   // offset_2
__device__ float g_om  [(size_t)BB * 27 * HW];   // offset/mask conv output
__device__ float g_align[(size_t)BB * 64 * HW];  // dcn output (pre out-conv)
__device__ float g_wt  [9 * 64 * 64];            // w_dcn transposed [k][c][oc]

// ---------------------------------------------------------------------------
// 3x3 SAME conv, NCHW, OIHW. Tile 64(w) x 4(h). 256 threads =
// 16(tx) x 4(ty) x 4(og). Thread = 4 px x 4 oc (2 f32x2 pairs).
// cp.async 3-stage ring: phase p+2's patch+weights stream in during
// compute(p)/compute(p+1); one barrier per phase. 4 blocks/SM.
// IC may be 128 (two-pointer concat). ACT: 0 none, 1 lrelu(0.1), 2 relu.
// ---------------------------------------------------------------------------
template<int IC, int ACT>
__global__ __launch_bounds__(256, 4)
void conv3x3_kernel(const float* __restrict__ in0, const float* __restrict__ in1,
                    const float* __restrict__ w, const float* __restrict__ bias,
                    float* __restrict__ out, int n_ocb, int OC)
{
    constexpr int ICS   = 4;
    constexpr int RS    = 68;                 // padded patch row stride (66 used)
    constexpr int PH    = 6;                  // 4 rows + halo
    constexpr int PATCH = ICS * PH * RS;      // 1632 floats
    constexpr int NW    = ICS * 9 * 16;       // 576 weights per phase
    constexpr int STG   = PATCH + NW;         // 2208 floats per stage
    constexpr int NP    = IC / ICS;           // phases

    __shared__ __align__(16) float ring[3][STG];

    const int tid = threadIdx.x;
    const int tx  = tid & 15;
    const int ty  = (tid >> 4) & 3;
    const int og  = tid >> 6;                 // 0..3: which 4-oc quarter
    const int bx  = blockIdx.x * 64;
    const int by  = blockIdx.y * 4;
    const int b   = blockIdx.z / n_ocb;
    const int ocb = blockIdx.z - b * n_ocb;
    const int oc0 = ocb * 16 + og * 4;

    // ---- loop-invariant staging offsets (computed once) ----
    int aoff[7];
#pragma unroll
    for (int s = 0; s < 7; ++s) {
        int pos = tid + 256 * s;
        int ics = pos / (PH * RS);
        int r2  = pos - ics * (PH * RS);
        int r   = r2 / RS, c = r2 - r * RS;
        int gy = by + r - 1, gx = bx + c - 1;
        bool ok = (pos < PATCH) && (c < 66) &&
                  ((unsigned)gy < HH) && ((unsigned)gx < WW);
        aoff[s] = ok ? (ics * HW + gy * WW + gx) : -1;
    }
    int woff[3];
#pragma unroll
    for (int s = 0; s < 3; ++s) {
        int pos = tid + 256 * s;
        int ics = pos / 144;
        int r   = pos - ics * 144;
        int k   = r >> 4, oc = r & 15;
        int ocg = ocb * 16 + oc;
        woff[s] = (pos < NW && ocg < OC) ? ((ocg * IC + ics) * 9 + k) : -1;
    }

    const float* base0 = in0 + (size_t)b * 64 * HW;
    const float* base1 = (IC > 64) ? (in1 + (size_t)b * 64 * HW) : in0;
    const u32 smbase = (u32)__cvta_generic_to_shared(&ring[0][0]);

    auto issue = [&](int p) {
        int ic0 = p * ICS;
        const float* src = (IC > 64 && ic0 >= 64) ? (base1 + (size_t)(ic0 - 64) * HW)
                                                  : (base0 + (size_t)ic0 * HW);
        u32 dst = smbase + (u32)(p % 3) * (STG * 4);
#pragma unroll
        for (int s = 0; s < 7; ++s) {
            int pos = tid + 256 * s;
            if (pos < PATCH) {
                int o = aoff[s];
                cp_async4(dst + pos * 4, (o >= 0) ? (src + o) : src, (o >= 0) ? 4 : 0);
            }
        }
        const float* wsrc = w + ic0 * 9;
#pragma unroll
        for (int s = 0; s < 3; ++s) {
            int pos = tid + 256 * s;
            if (pos < NW) {
                int o = woff[s];
                cp_async4(dst + (PATCH + pos) * 4, (o >= 0) ? (wsrc + o) : wsrc,
                          (o >= 0) ? 4 : 0);
            }
        }
    };

    ull acc[2][4];                            // [oc pair][px]
#pragma unroll
    for (int o = 0; o < 2; ++o)
#pragma unroll
        for (int p = 0; p < 4; ++p) acc[o][p] = 0ull;

    issue(0); cp_commit();
    issue(1); cp_commit();

    for (int p = 0; p < NP; ++p) {
        cp_wait1();                           // group p complete (this thread)
        __syncthreads();                      // block-wide visibility + retire p-1 readers
        if (p + 2 < NP) issue(p + 2);         // safe: buf[(p+2)%3]=buf[(p-1)%3] now free
        cp_commit();                          // empty group in tail keeps wait_group 1 valid

        const float* stage = ring[p % 3];
#pragma unroll
        for (int ics = 0; ics < ICS; ++ics) {
            const float* prow = stage + ics * (PH * RS);
            const float* wrow = stage + PATCH + ics * 144;
#pragma unroll
            for (int ky = 0; ky < 3; ++ky) {
                int bp = (ty + ky) * RS + tx * 4;
                float4 a0 = *reinterpret_cast<const float4*>(prow + bp);
                float2 a1 = *reinterpret_cast<const float2*>(prow + bp + 4);
                ull pv[6];
                pv[0] = pack2(a0.x, a0.x); pv[1] = pack2(a0.y, a0.y);
                pv[2] = pack2(a0.z, a0.z); pv[3] = pack2(a0.w, a0.w);
                pv[4] = pack2(a1.x, a1.x); pv[5] = pack2(a1.y, a1.y);
#pragma unroll
                for (int kx = 0; kx < 3; ++kx) {
                    ulonglong2 w0 = *reinterpret_cast<const ulonglong2*>(
                        wrow + (ky * 3 + kx) * 16 + og * 4);
#pragma unroll
                    for (int q = 0; q < 4; ++q) {
                        fma2(acc[0][q], pv[kx + q], w0.x);
                        fma2(acc[1][q], pv[kx + q], w0.y);
                    }
                }
            }
        }
    }

    const int py = by + ty;
    const int px = bx + tx * 4;
#pragma unroll
    for (int op = 0; op < 2; ++op) {
        float2 a[4];
#pragma unroll
        for (int p = 0; p < 4; ++p) a[p] = unpack2(acc[op][p]);
        int oce = oc0 + 2 * op;
#pragma unroll
        for (int lane = 0; lane < 2; ++lane) {
            int oc = oce + lane;
            if (oc >= OC) continue;
            float bv = bias[oc];
            float rr[4];
#pragma unroll
            for (int p = 0; p < 4; ++p) {
                float vv = (lane == 0 ? a[p].x : a[p].y) + bv;
                if (ACT == 1) vv = (vv >= 0.f) ? vv : 0.1f * vv;
                if (ACT == 2) vv = fmaxf(vv, 0.f);
                rr[p] = vv;
            }
            float4 r4; r4.x = rr[0]; r4.y = rr[1]; r4.z = rr[2]; r4.w = rr[3];
            *reinterpret_cast<float4*>(
                &out[((size_t)b * OC + oc) * HW + (size_t)py * WW + px]) = r4;
        }
    }
}

// ---------------------------------------------------------------------------
// One-off: transpose w_dcn [oc][c][k] -> [k][c][oc] so DCN staging coalesces.
// ---------------------------------------------------------------------------
__global__ void transpose_wd_kernel(const float* __restrict__ wd,
                                    float* __restrict__ wt)
{
    int i = blockIdx.x * 256 + threadIdx.x;      // 9*64*64 = 36864
    if (i < 9 * 64 * 64) {
        int k = i >> 12;
        int r = i & 4095;
        int c = r >> 6, oc = r & 63;
        wt[i] = wd[((size_t)oc * 64 + c) * 9 + k];
    }
}

// ---------------------------------------------------------------------------
// Deformable conv core. Thread = 1 pixel, 32 f32x2 oc-pair accumulators.
// Weight slice for tap k+2 streams in via cp.async during compute(k).
// ---------------------------------------------------------------------------
__global__ __launch_bounds__(256, 2)
void dcn_kernel(const float* __restrict__ x, const float* __restrict__ om,
                const float* __restrict__ wt, const float* __restrict__ bias,
                float* __restrict__ out)
{
    __shared__ __align__(16) float ring[3][4096];  // [c][oc] slices

    const int tid  = threadIdx.x;
    const int px0  = tid & 127;
    const int wrow = tid >> 7;
    const int b    = blockIdx.y;
    const int py0  = blockIdx.x * 2 + wrow;
    const int hw   = py0 * WW + px0;

    const float* omb = om + (size_t)b * 27 * HW;
    const float* xb  = x  + (size_t)b * 64 * HW;
    const u32 smbase = (u32)__cvta_generic_to_shared(&ring[0][0]);

    auto issueW = [&](int k) {
        u32 dst = smbase + (u32)(k % 3) * (4096 * 4);
        const float* src = wt + (size_t)k * 4096;
#pragma unroll
        for (int s = 0; s < 4; ++s) {
            int slot = tid + 256 * s;                 // float4 slot
            cp_async16(dst + slot * 16, src + slot * 4);
        }
    };

    ull acc[32];
#pragma unroll
    for (int o = 0; o < 32; ++o) acc[o] = 0ull;

    issueW(0); cp_commit();
    issueW(1); cp_commit();

    for (int k = 0; k < 9; ++k) {
        cp_wait1();
        __syncthreads();
        if (k + 2 < 9) issueW(k + 2);
        cp_commit();

        const float* wk = ring[k % 3];

        float oy = omb[(size_t)k * HW + hw];
        float ox = omb[(size_t)(9 + k) * HW + hw];
        float mr = omb[(size_t)(18 + k) * HW + hw];
        float m  = 1.f / (1.f + __expf(-mr));

        int   ky = k / 3, kx = k - ky * 3;
        float py = (float)(py0 - 1 + ky) + oy;
        float px = (float)(px0 - 1 + kx) + ox;
        float y0f = floorf(py), x0f = floorf(px);
        float ly = py - y0f, lx = px - x0f;
        int y0 = (int)y0f, x0 = (int)x0f;
        int y1 = y0 + 1,   x1 = x0 + 1;

        float vy0 = (y0 >= 0 && y0 <= HH - 1) ? 1.f : 0.f;
        float vy1 = (y1 >= 0 && y1 <= HH - 1) ? 1.f : 0.f;
        float vx0 = (x0 >= 0 && x0 <= WW - 1) ? 1.f : 0.f;
        float vx1 = (x1 >= 0 && x1 <= WW - 1) ? 1.f : 0.f;
        int y0c = min(max(y0, 0), HH - 1), y1c = min(max(y1, 0), HH - 1);
        int x0c = min(max(x0, 0), WW - 1), x1c = min(max(x1, 0), WW - 1);

        float w00 = (1.f - ly) * (1.f - lx) * m * vy0 * vx0;
        float w01 = (1.f - ly) * lx         * m * vy0 * vx1;
        float w10 = ly         * (1.f - lx) * m * vy1 * vx0;
        float w11 = ly         * lx         * m * vy1 * vx1;

        int i00 = y0c * WW + x0c, i01 = y0c * WW + x1c;
        int i10 = y1c * WW + x0c, i11 = y1c * WW + x1c;

        const float* xc = xb;
#pragma unroll 2
        for (int c = 0; c < 64; ++c, xc += HW) {
            float s = w00 * xc[i00];
            s = fmaf(w01, xc[i01], s);
            s = fmaf(w10, xc[i10], s);
            s = fmaf(w11, xc[i11], s);
            ull ss = pack2(s, s);
            const ulonglong2* wr = reinterpret_cast<const ulonglong2*>(&wk[c * 64]);
#pragma unroll
            for (int j = 0; j < 16; ++j) {
                ulonglong2 q = wr[j];
                fma2(acc[2 * j],     ss, q.x);
                fma2(acc[2 * j + 1], ss, q.y);
            }
        }
    }

#pragma unroll
    for (int j = 0; j < 32; ++j) {
        float2 a = unpack2(acc[j]);
        int oc = 2 * j;
        out[((size_t)b * 64 + oc)     * HW + hw] = a.x + bias[oc];
        out[((size_t)b * 64 + oc + 1) * HW + hw] = a.y + bias[oc + 1];
    }
}

// ---------------------------------------------------------------------------
extern "C" void kernel_launch(void* const* d_in, const int* in_sizes, int n_in,
                              void* d_out, int out_size)
{
    const float* x        = (const float*)d_in[0];
    const float* x_neigh  = (const float*)d_in[1];
    const float* offset_t = (const float*)d_in[2];
    const float* w_off1   = (const float*)d_in[3];
    const float* b_off1   = (const float*)d_in[4];
    const float* w_off2   = (const float*)d_in[5];
    const float* b_off2   = (const float*)d_in[6];
    const float* w_off3   = (const float*)d_in[7];
    const float* b_off3   = (const float*)d_in[8];
    const float* w_om     = (const float*)d_in[9];
    const float* b_om     = (const float*)d_in[10];
    const float* w_dcn    = (const float*)d_in[11];
    const float* b_dcn    = (const float*)d_in[12];
    const float* w_outw   = (const float*)d_in[13];
    const float* b_outw   = (const float*)d_in[14];

    float* out        = (float*)d_out;
    float* out_align  = out;                              // (4,64,128,128)
    float* out_offset = out + (size_t)BB * 64 * HW;       // (4,64,128,128)

    float *p1, *p2, *pom, *pal, *pwt;
    cudaGetSymbolAddress((void**)&p1,  g_buf1);
    cudaGetSymbolAddress((void**)&p2,  g_buf2);
    cudaGetSymbolAddress((void**)&pom, g_om);
    cudaGetSymbolAddress((void**)&pal, g_align);
    cudaGetSymbolAddress((void**)&pwt, g_wt);

    dim3 blk(256);
    dim3 g64(2, 32, BB * 4);  // 64 oc -> 4 oc-blocks of 16; 1024 blocks
    dim3 gom(2, 32, BB * 2);  // 27 oc -> 2 oc-blocks of 16 (guarded); 512 blocks

    transpose_wd_kernel<<<144, blk>>>(w_dcn, pwt);

    conv3x3_kernel<128, 1><<<g64, blk>>>(x, x_neigh, w_off1, b_off1, p1, 4, 64);
    conv3x3_kernel<128, 1><<<g64, blk>>>(p1, offset_t, w_off2, b_off2, p2, 4, 64);
    conv3x3_kernel<64, 1><<<g64, blk>>>(p2, nullptr, w_off3, b_off3, out_offset, 4, 64);
    conv3x3_kernel<64, 0><<<gom, blk>>>(out_offset, nullptr, w_om, b_om, pom, 2, 27);

    dim3 gd(64, BB);
    dcn_kernel<<<gd, blk>>>(x, pom, pwt, b_dcn, pal);

    conv3x3_kernel<64, 2><<<g64, blk>>>(pal, nullptr, w_outw, b_outw, out_align, 4, 64);
}

// round 8
// speedup vs baseline: 1.7593x; 1.7593x over previous
#include <cuda_runtime.h>

#define HH 128
#define WW 128
#define HW (HH * WW)
#define BB 4

typedef unsigned long long ull;
typedef unsigned int u32;

__device__ __forceinline__ ull pack2(float lo, float hi) {
    ull r; asm("mov.b64 %0,{%1,%2};" : "=l"(r) : "f"(lo), "f"(hi)); return r;
}
__device__ __forceinline__ float2 unpack2(ull v) {
    float2 r; asm("mov.b64 {%0,%1},%2;" : "=f"(r.x), "=f"(r.y) : "l"(v)); return r;
}
// d = a*b + d  (two independent fp32 FMAs per instruction)
__device__ __forceinline__ void fma2(ull& d, ull a, ull b) {
    asm("fma.rn.f32x2 %0,%1,%2,%0;" : "+l"(d) : "l"(a), "l"(b));
}
// async 16B copy, zero-fill when sz==0
__device__ __forceinline__ void cp_async16z(u32 dst, const void* src, int sz) {
    asm volatile("cp.async.cg.shared.global [%0], [%1], 16, %2;"
                 :: "r"(dst), "l"(src), "r"(sz));
}
__device__ __forceinline__ void cp_async16(u32 dst, const void* src) {
    asm volatile("cp.async.cg.shared.global [%0], [%1], 16;"
                 :: "r"(dst), "l"(src));
}
__device__ __forceinline__ void cp_commit() {
    asm volatile("cp.async.commit_group;");
}
__device__ __forceinline__ void cp_wait1() {
    asm volatile("cp.async.wait_group 1;");
}

// Scratch (allocation-free rule: __device__ globals)
__device__ float g_buf1[(size_t)BB * 64 * HW];   // offset_1
__device__ float g_buf2[(size_t)BB * 64 * HW];   // offset_2
__device__ float g_om  [(size_t)BB * 27 * HW];   // offset/mask conv output
__device__ float g_align[(size_t)BB * 64 * HW];  // dcn output (pre out-conv)
__device__ float g_wt  [9 * 64 * 64];            // w_dcn transposed [k][c][oc]
// conv weights transposed to [ic][k][ocp] (oc-contiguous, padded stride)
__device__ float g_wt1[128 * 9 * 64];
__device__ float g_wt2[128 * 9 * 64];
__device__ float g_wt3[64 * 9 * 64];
__device__ float g_wtm[64 * 9 * 32];             // om conv: OC=27 padded to 32
__device__ float g_wto[64 * 9 * 64];

// ---------------------------------------------------------------------------
// One-off: transpose conv weights [oc][ic][k] -> [ic][k][ocp] (zero-padded).
// ---------------------------------------------------------------------------
__global__ void transpose_w_kernel(const float* __restrict__ w,
                                   float* __restrict__ wt,
                                   int OC, int IC, int OCP)
{
    int i = blockIdx.x * 256 + threadIdx.x;
    int total = IC * 9 * OCP;
    if (i < total) {
        int oc = i % OCP;
        int t  = i / OCP;
        int k  = t % 9;
        int ic = t / 9;
        wt[i] = (oc < OC) ? w[((size_t)oc * IC + ic) * 9 + k] : 0.f;
    }
}

// ---------------------------------------------------------------------------
// 3x3 SAME conv, NCHW. Tile 64(w) x 8(h). 256 threads =
// 16(tx) x 8(ty) x 2(og). Thread = 4 px x 8 oc (4 f32x2 pairs).
// All staging via aligned cp.async16 (patch cols bx-4..bx+67, RS=72;
// weights pre-transposed oc-contiguous). 3-stage ring, 1 barrier/phase.
// IC may be 128 (two-pointer concat). ACT: 0 none, 1 lrelu(0.1), 2 relu.
// ---------------------------------------------------------------------------
template<int IC, int ACT, int OCP>
__global__ __launch_bounds__(256, 3)
void conv3x3_kernel(const float* __restrict__ in0, const float* __restrict__ in1,
                    const float* __restrict__ wtc, const float* __restrict__ bias,
                    float* __restrict__ out, int n_ocb, int OC)
{
    constexpr int ICS   = 4;
    constexpr int RS    = 72;                 // patch row stride (cols bx-4..bx+67)
    constexpr int PH    = 10;                 // 8 rows + halo
    constexpr int PATCH = ICS * PH * RS;      // 2880 floats
    constexpr int P4    = PATCH / 4;          // 720 float4 slots
    constexpr int NW    = ICS * 9 * 16;       // 576 weights per phase
    constexpr int STG   = PATCH + NW;         // 3456 floats per stage
    constexpr int NP    = IC / ICS;           // phases

    __shared__ __align__(16) float ring[3][STG];

    const int tid = threadIdx.x;
    const int tx  = tid & 15;
    const int ty  = (tid >> 4) & 7;
    const int og  = tid >> 7;                 // 0/1: which 8-oc half
    const int bx  = blockIdx.x * 64;
    const int by  = blockIdx.y * 8;
    const int b   = blockIdx.z / n_ocb;
    const int ocb = blockIdx.z - b * n_ocb;
    const int oc0 = ocb * 16 + og * 8;

    // ---- loop-invariant staging offsets ----
    int aoff[3];
#pragma unroll
    for (int s = 0; s < 3; ++s) {
        int q = tid + 256 * s;
        int ics = q / 180;
        int r2  = q - ics * 180;
        int r   = r2 / 18, c4 = r2 - r * 18;
        int gy = by + r - 1;
        int gx = bx - 4 + c4 * 4;             // float4 fully in [0,124] or fully OOB
        bool ok = (q < P4) && ((unsigned)gy < HH) && ((unsigned)gx <= 124u);
        aoff[s] = ok ? (ics * HW + gy * WW + gx) : -1;
    }
    int woffc = 0, wdst = 0;                  // weight slot (tid < 144)
    {
        int ics = tid / 36;
        int r   = tid - ics * 36;
        int k   = r >> 2, c4 = r & 3;
        woffc = (ics * 9 + k) * OCP + ocb * 16 + c4 * 4;
        wdst  = (ics * 9 + k) * 16 + c4 * 4;
    }

    const float* base0 = in0 + (size_t)b * 64 * HW;
    const float* base1 = (IC > 64) ? (in1 + (size_t)b * 64 * HW) : in0;
    const u32 smbase = (u32)__cvta_generic_to_shared(&ring[0][0]);

    auto issue = [&](int p) {
        int ic0 = p * ICS;
        const float* src = (IC > 64 && ic0 >= 64) ? (base1 + (size_t)(ic0 - 64) * HW)
                                                  : (base0 + (size_t)ic0 * HW);
        u32 dst = smbase + (u32)(p % 3) * (STG * 4);
#pragma unroll
        for (int s = 0; s < 3; ++s) {
            int q = tid + 256 * s;
            if (q < P4) {
                int o = aoff[s];
                cp_async16z(dst + q * 16, (o >= 0) ? (src + o) : src, (o >= 0) ? 16 : 0);
            }
        }
        if (tid < 144)
            cp_async16(dst + (PATCH + wdst) * 4, wtc + (size_t)ic0 * 9 * OCP + woffc);
    };

    ull acc[4][4];                            // [oc pair][px]
#pragma unroll
    for (int o = 0; o < 4; ++o)
#pragma unroll
        for (int p = 0; p < 4; ++p) acc[o][p] = 0ull;

    issue(0); cp_commit();
    issue(1); cp_commit();

    for (int p = 0; p < NP; ++p) {
        cp_wait1();                           // group p complete (this thread)
        __syncthreads();                      // visibility + retire p-1 readers
        if (p + 2 < NP) issue(p + 2);         // buf[(p+2)%3]=buf[(p-1)%3] now free
        cp_commit();                          // empty tail group keeps wait_group 1 valid

        const float* stage = ring[p % 3];
#pragma unroll
        for (int ics = 0; ics < ICS; ++ics) {
            const float* prow = stage + ics * (PH * RS);
            const float* wrow = stage + PATCH + ics * 144;
#pragma unroll
            for (int ky = 0; ky < 3; ++ky) {
                // activation cols (patch-relative): tx*4+3 .. tx*4+8
                int j0 = (ty + ky) * RS + tx * 4 + 2;
                float2 lo  = *reinterpret_cast<const float2*>(prow + j0);
                float4 mid = *reinterpret_cast<const float4*>(prow + j0 + 2);
                float2 hi  = *reinterpret_cast<const float2*>(prow + j0 + 6);
                ull pv[6];
                pv[0] = pack2(lo.y,  lo.y);
                pv[1] = pack2(mid.x, mid.x); pv[2] = pack2(mid.y, mid.y);
                pv[3] = pack2(mid.z, mid.z); pv[4] = pack2(mid.w, mid.w);
                pv[5] = pack2(hi.x,  hi.x);
#pragma unroll
                for (int kx = 0; kx < 3; ++kx) {
                    const ulonglong2* wr = reinterpret_cast<const ulonglong2*>(
                        wrow + (ky * 3 + kx) * 16 + og * 8);
                    ulonglong2 w0 = wr[0];
                    ulonglong2 w1 = wr[1];
#pragma unroll
                    for (int q = 0; q < 4; ++q) {
                        fma2(acc[0][q], pv[kx + q], w0.x);
                        fma2(acc[1][q], pv[kx + q], w0.y);
                        fma2(acc[2][q], pv[kx + q], w1.x);
                        fma2(acc[3][q], pv[kx + q], w1.y);
                    }
                }
            }
        }
    }

    const int py = by + ty;
    const int px = bx + tx * 4;
#pragma unroll
    for (int op = 0; op < 4; ++op) {
        float2 a[4];
#pragma unroll
        for (int p = 0; p < 4; ++p) a[p] = unpack2(acc[op][p]);
        int oce = oc0 + 2 * op;
#pragma unroll
        for (int lane = 0; lane < 2; ++lane) {
            int oc = oce + lane;
            if (oc >= OC) continue;
            float bv = bias[oc];
            float rr[4];
#pragma unroll
            for (int p = 0; p < 4; ++p) {
                float vv = (lane == 0 ? a[p].x : a[p].y) + bv;
                if (ACT == 1) vv = (vv >= 0.f) ? vv : 0.1f * vv;
                if (ACT == 2) vv = fmaxf(vv, 0.f);
                rr[p] = vv;
            }
            float4 r4; r4.x = rr[0]; r4.y = rr[1]; r4.z = rr[2]; r4.w = rr[3];
            *reinterpret_cast<float4*>(
                &out[((size_t)b * OC + oc) * HW + (size_t)py * WW + px]) = r4;
        }
    }
}

// ---------------------------------------------------------------------------
// One-off: transpose w_dcn [oc][c][k] -> [k][c][oc] so DCN staging coalesces.
// ---------------------------------------------------------------------------
__global__ void transpose_wd_kernel(const float* __restrict__ wd,
                                    float* __restrict__ wt)
{
    int i = blockIdx.x * 256 + threadIdx.x;      // 9*64*64 = 36864
    if (i < 9 * 64 * 64) {
        int k = i >> 12;
        int r = i & 4095;
        int c = r >> 6, oc = r & 63;
        wt[i] = wd[((size_t)oc * 64 + c) * 9 + k];
    }
}

// ---------------------------------------------------------------------------
// Deformable conv core. Thread = 1 pixel, 32 f32x2 oc-pair accumulators.
// Weight slice for tap k+2 streams in via cp.async during compute(k).
// ---------------------------------------------------------------------------
__global__ __launch_bounds__(256, 2)
void dcn_kernel(const float* __restrict__ x, const float* __restrict__ om,
                const float* __restrict__ wt, const float* __restrict__ bias,
                float* __restrict__ out)
{
    __shared__ __align__(16) float ring[3][4096];  // [c][oc] slices

    const int tid  = threadIdx.x;
    const int px0  = tid & 127;
    const int wrow = tid >> 7;
    const int b    = blockIdx.y;
    const int py0  = blockIdx.x * 2 + wrow;
    const int hw   = py0 * WW + px0;

    const float* omb = om + (size_t)b * 27 * HW;
    const float* xb  = x  + (size_t)b * 64 * HW;
    const u32 smbase = (u32)__cvta_generic_to_shared(&ring[0][0]);

    auto issueW = [&](int k) {
        u32 dst = smbase + (u32)(k % 3) * (4096 * 4);
        const float* src = wt + (size_t)k * 4096;
#pragma unroll
        for (int s = 0; s < 4; ++s) {
            int slot = tid + 256 * s;                 // float4 slot
            cp_async16(dst + slot * 16, src + slot * 4);
        }
    };

    ull acc[32];
#pragma unroll
    for (int o = 0; o < 32; ++o) acc[o] = 0ull;

    issueW(0); cp_commit();
    issueW(1); cp_commit();

    for (int k = 0; k < 9; ++k) {
        cp_wait1();
        __syncthreads();
        if (k + 2 < 9) issueW(k + 2);
        cp_commit();

        const float* wk = ring[k % 3];

        float oy = omb[(size_t)k * HW + hw];
        float ox = omb[(size_t)(9 + k) * HW + hw];
        float mr = omb[(size_t)(18 + k) * HW + hw];
        float m  = 1.f / (1.f + __expf(-mr));

        int   ky = k / 3, kx = k - ky * 3;
        float py = (float)(py0 - 1 + ky) + oy;
        float px = (float)(px0 - 1 + kx) + ox;
        float y0f = floorf(py), x0f = floorf(px);
        float ly = py - y0f, lx = px - x0f;
        int y0 = (int)y0f, x0 = (int)x0f;
        int y1 = y0 + 1,   x1 = x0 + 1;

        float vy0 = (y0 >= 0 && y0 <= HH - 1) ? 1.f : 0.f;
        float vy1 = (y1 >= 0 && y1 <= HH - 1) ? 1.f : 0.f;
        float vx0 = (x0 >= 0 && x0 <= WW - 1) ? 1.f : 0.f;
        float vx1 = (x1 >= 0 && x1 <= WW - 1) ? 1.f : 0.f;
        int y0c = min(max(y0, 0), HH - 1), y1c = min(max(y1, 0), HH - 1);
        int x0c = min(max(x0, 0), WW - 1), x1c = min(max(x1, 0), WW - 1);

        float w00 = (1.f - ly) * (1.f - lx) * m * vy0 * vx0;
        float w01 = (1.f - ly) * lx         * m * vy0 * vx1;
        float w10 = ly         * (1.f - lx) * m * vy1 * vx0;
        float w11 = ly         * lx         * m * vy1 * vx1;

        int i00 = y0c * WW + x0c, i01 = y0c * WW + x1c;
        int i10 = y1c * WW + x0c, i11 = y1c * WW + x1c;

        const float* xc = xb;
#pragma unroll 2
        for (int c = 0; c < 64; ++c, xc += HW) {
            float s = w00 * xc[i00];
            s = fmaf(w01, xc[i01], s);
            s = fmaf(w10, xc[i10], s);
            s = fmaf(w11, xc[i11], s);
            ull ss = pack2(s, s);
            const ulonglong2* wr = reinterpret_cast<const ulonglong2*>(&wk[c * 64]);
#pragma unroll
            for (int j = 0; j < 16; ++j) {
                ulonglong2 q = wr[j];
                fma2(acc[2 * j],     ss, q.x);
                fma2(acc[2 * j + 1], ss, q.y);
            }
        }
    }

#pragma unroll
    for (int j = 0; j < 32; ++j) {
        float2 a = unpack2(acc[j]);
        int oc = 2 * j;
        out[((size_t)b * 64 + oc)     * HW + hw] = a.x + bias[oc];
        out[((size_t)b * 64 + oc + 1) * HW + hw] = a.y + bias[oc + 1];
    }
}

// ---------------------------------------------------------------------------
extern "C" void kernel_launch(void* const* d_in, const int* in_sizes, int n_in,
                              void* d_out, int out_size)
{
    const float* x        = (const float*)d_in[0];
    const float* x_neigh  = (const float*)d_in[1];
    const float* offset_t = (const float*)d_in[2];
    const float* w_off1   = (const float*)d_in[3];
    const float* b_off1   = (const float*)d_in[4];
    const float* w_off2   = (const float*)d_in[5];
    const float* b_off2   = (const float*)d_in[6];
    const float* w_off3   = (const float*)d_in[7];
    const float* b_off3   = (const float*)d_in[8];
    const float* w_om     = (const float*)d_in[9];
    const float* b_om     = (const float*)d_in[10];
    const float* w_dcn    = (const float*)d_in[11];
    const float* b_dcn    = (const float*)d_in[12];
    const float* w_outw   = (const float*)d_in[13];
    const float* b_outw   = (const float*)d_in[14];

    float* out        = (float*)d_out;
    float* out_align  = out;                              // (4,64,128,128)
    float* out_offset = out + (size_t)BB * 64 * HW;       // (4,64,128,128)

    float *p1, *p2, *pom, *pal, *pwt;
    float *pw1, *pw2, *pw3, *pwm, *pwo;
    cudaGetSymbolAddress((void**)&p1,  g_buf1);
    cudaGetSymbolAddress((void**)&p2,  g_buf2);
    cudaGetSymbolAddress((void**)&pom, g_om);
    cudaGetSymbolAddress((void**)&pal, g_align);
    cudaGetSymbolAddress((void**)&pwt, g_wt);
    cudaGetSymbolAddress((void**)&pw1, g_wt1);
    cudaGetSymbolAddress((void**)&pw2, g_wt2);
    cudaGetSymbolAddress((void**)&pw3, g_wt3);
    cudaGetSymbolAddress((void**)&pwm, g_wtm);
    cudaGetSymbolAddress((void**)&pwo, g_wto);

    dim3 blk(256);
    dim3 g64(2, 16, BB * 4);  // 64 oc -> 4 oc-blocks of 16; 512 blocks
    dim3 gom(2, 16, BB * 2);  // 27 oc -> 2 oc-blocks of 16 (guarded); 256 blocks

    // one-off weight transposes (tiny)
    transpose_w_kernel<<<(128 * 9 * 64 + 255) / 256, blk>>>(w_off1, pw1, 64, 128, 64);
    transpose_w_kernel<<<(128 * 9 * 64 + 255) / 256, blk>>>(w_off2, pw2, 64, 128, 64);
    transpose_w_kernel<<<(64 * 9 * 64 + 255) / 256, blk>>>(w_off3, pw3, 64, 64, 64);
    transpose_w_kernel<<<(64 * 9 * 32 + 255) / 256, blk>>>(w_om,   pwm, 27, 64, 32);
    transpose_w_kernel<<<(64 * 9 * 64 + 255) / 256, blk>>>(w_outw, pwo, 64, 64, 64);
    transpose_wd_kernel<<<144, blk>>>(w_dcn, pwt);

    conv3x3_kernel<128, 1, 64><<<g64, blk>>>(x, x_neigh, pw1, b_off1, p1, 4, 64);
    conv3x3_kernel<128, 1, 64><<<g64, blk>>>(p1, offset_t, pw2, b_off2, p2, 4, 64);
    conv3x3_kernel<64, 1, 64><<<g64, blk>>>(p2, nullptr, pw3, b_off3, out_offset, 4, 64);
    conv3x3_kernel<64, 0, 32><<<gom, blk>>>(out_offset, nullptr, pwm, b_om, pom, 2, 27);

    dim3 gd(64, BB);
    dcn_kernel<<<gd, blk>>>(x, pom, pwt, b_dcn, pal);

    conv3x3_kernel<64, 2, 64><<<g64, blk>>>(pal, nullptr, pwo, b_outw, out_align, 4, 64);
}

// round 9
// speedup vs baseline: 1.7899x; 1.0174x over previous
#include <cuda_runtime.h>

#define HH 128
#define WW 128
#define HW (HH * WW)
#define BB 4

typedef unsigned long long ull;
typedef unsigned int u32;

__device__ __forceinline__ ull pack2(float lo, float hi) {
    ull r; asm("mov.b64 %0,{%1,%2};" : "=l"(r) : "f"(lo), "f"(hi)); return r;
}
__device__ __forceinline__ float2 unpack2(ull v) {
    float2 r; asm("mov.b64 {%0,%1},%2;" : "=f"(r.x), "=f"(r.y) : "l"(v)); return r;
}
// d = a*b + d  (two independent fp32 FMAs per instruction)
__device__ __forceinline__ void fma2(ull& d, ull a, ull b) {
    asm("fma.rn.f32x2 %0,%1,%2,%0;" : "+l"(d) : "l"(a), "l"(b));
}
// async 16B copy, zero-fill when sz==0
__device__ __forceinline__ void cp_async16z(u32 dst, const void* src, int sz) {
    asm volatile("cp.async.cg.shared.global [%0], [%1], 16, %2;"
                 :: "r"(dst), "l"(src), "r"(sz));
}
__device__ __forceinline__ void cp_async16(u32 dst, const void* src) {
    asm volatile("cp.async.cg.shared.global [%0], [%1], 16;"
                 :: "r"(dst), "l"(src));
}
__device__ __forceinline__ void cp_commit() {
    asm volatile("cp.async.commit_group;");
}
__device__ __forceinline__ void cp_wait1() {
    asm volatile("cp.async.wait_group 1;");
}

// Scratch (allocation-free rule: __device__ globals)
__device__ float g_buf1[(size_t)BB * 64 * HW];   // offset_1
__device__ float g_buf2[(size_t)BB * 64 * HW];   // offset_2
__device__ float g_om  [(size_t)BB * 27 * HW];   // offset/mask conv output
__device__ float g_align[(size_t)BB * 64 * HW];  // dcn output (pre out-conv)
__device__ float g_wt  [9 * 64 * 64];            // w_dcn transposed [k][c][oc]
// conv weights transposed to [ic][k][ocp] (oc-contiguous, padded stride)
__device__ float g_wt1[128 * 9 * 64];
__device__ float g_wt2[128 * 9 * 64];
__device__ float g_wt3[64 * 9 * 64];
__device__ float g_wtm[64 * 9 * 32];             // om conv: OC=27 padded to 32
__device__ float g_wto[64 * 9 * 64];

// ---------------------------------------------------------------------------
// One-off merged transpose: all five conv weights [oc][ic][k] -> [ic][k][ocp]
// plus w_dcn [oc][c][k] -> [k][c][oc], in a single launch.
// ---------------------------------------------------------------------------
#define N1 (128 * 9 * 64)
#define N2 (128 * 9 * 64)
#define N3 (64 * 9 * 64)
#define NM (64 * 9 * 32)
#define NO (64 * 9 * 64)
#define ND (9 * 64 * 64)
#define NT (N1 + N2 + N3 + NM + NO + ND)

__device__ __forceinline__ void tr_conv(const float* w, float* wt, int i,
                                        int OC, int IC, int OCP)
{
    int oc = i % OCP;
    int t  = i / OCP;
    int k  = t % 9;
    int ic = t / 9;
    wt[i] = (oc < OC) ? w[((size_t)oc * IC + ic) * 9 + k] : 0.f;
}

__global__ void transpose_all_kernel(
    const float* __restrict__ w1, const float* __restrict__ w2,
    const float* __restrict__ w3, const float* __restrict__ wm,
    const float* __restrict__ wo, const float* __restrict__ wd,
    float* __restrict__ o1, float* __restrict__ o2, float* __restrict__ o3,
    float* __restrict__ om, float* __restrict__ oo, float* __restrict__ od)
{
    int i = blockIdx.x * 256 + threadIdx.x;
    if (i < N1) { tr_conv(w1, o1, i, 64, 128, 64); return; }
    i -= N1;
    if (i < N2) { tr_conv(w2, o2, i, 64, 128, 64); return; }
    i -= N2;
    if (i < N3) { tr_conv(w3, o3, i, 64, 64, 64); return; }
    i -= N3;
    if (i < NM) { tr_conv(wm, om, i, 27, 64, 32); return; }
    i -= NM;
    if (i < NO) { tr_conv(wo, oo, i, 64, 64, 64); return; }
    i -= NO;
    if (i < ND) {
        int k = i >> 12;
        int r = i & 4095;
        int c = r >> 6, oc = r & 63;
        od[i] = wd[((size_t)oc * 64 + c) * 9 + k];
    }
}

// ---------------------------------------------------------------------------
// 3x3 SAME conv, NCHW. Tile 64(w) x 8(h). 256 threads =
// 16(tx) x 8(ty) x 2(og). Thread = 4 px x 8 oc (4 f32x2 pairs).
// All staging via aligned cp.async16 (patch cols bx-4..bx+67, RS=72;
// weights pre-transposed oc-contiguous). 3-stage ring, 1 barrier/phase.
// IC may be 128 (two-pointer concat). ACT: 0 none, 1 lrelu(0.1), 2 relu.
// ---------------------------------------------------------------------------
template<int IC, int ACT, int OCP>
__global__ __launch_bounds__(256, 3)
void conv3x3_kernel(const float* __restrict__ in0, const float* __restrict__ in1,
                    const float* __restrict__ wtc, const float* __restrict__ bias,
                    float* __restrict__ out, int n_ocb, int OC)
{
    constexpr int ICS   = 4;
    constexpr int RS    = 72;                 // patch row stride (cols bx-4..bx+67)
    constexpr int PH    = 10;                 // 8 rows + halo
    constexpr int PATCH = ICS * PH * RS;      // 2880 floats
    constexpr int P4    = PATCH / 4;          // 720 float4 slots
    constexpr int NW    = ICS * 9 * 16;       // 576 weights per phase
    constexpr int STG   = PATCH + NW;         // 3456 floats per stage
    constexpr int NP    = IC / ICS;           // phases

    __shared__ __align__(16) float ring[3][STG];

    const int tid = threadIdx.x;
    const int tx  = tid & 15;
    const int ty  = (tid >> 4) & 7;
    const int og  = tid >> 7;                 // 0/1: which 8-oc half
    const int bx  = blockIdx.x * 64;
    const int by  = blockIdx.y * 8;
    const int b   = blockIdx.z / n_ocb;
    const int ocb = blockIdx.z - b * n_ocb;
    const int oc0 = ocb * 16 + og * 8;

    // ---- loop-invariant staging offsets ----
    int aoff[3];
#pragma unroll
    for (int s = 0; s < 3; ++s) {
        int q = tid + 256 * s;
        int ics = q / 180;
        int r2  = q - ics * 180;
        int r   = r2 / 18, c4 = r2 - r * 18;
        int gy = by + r - 1;
        int gx = bx - 4 + c4 * 4;             // float4 fully in [0,124] or fully OOB
        bool ok = (q < P4) && ((unsigned)gy < HH) && ((unsigned)gx <= 124u);
        aoff[s] = ok ? (ics * HW + gy * WW + gx) : -1;
    }
    int woffc = 0, wdst = 0;                  // weight slot (tid < 144)
    {
        int ics = tid / 36;
        int r   = tid - ics * 36;
        int k   = r >> 2, c4 = r & 3;
        woffc = (ics * 9 + k) * OCP + ocb * 16 + c4 * 4;
        wdst  = (ics * 9 + k) * 16 + c4 * 4;
    }

    const float* base0 = in0 + (size_t)b * 64 * HW;
    const float* base1 = (IC > 64) ? (in1 + (size_t)b * 64 * HW) : in0;
    const u32 smbase = (u32)__cvta_generic_to_shared(&ring[0][0]);

    auto issue = [&](int p) {
        int ic0 = p * ICS;
        const float* src = (IC > 64 && ic0 >= 64) ? (base1 + (size_t)(ic0 - 64) * HW)
                                                  : (base0 + (size_t)ic0 * HW);
        u32 dst = smbase + (u32)(p % 3) * (STG * 4);
#pragma unroll
        for (int s = 0; s < 3; ++s) {
            int q = tid + 256 * s;
            if (q < P4) {
                int o = aoff[s];
                cp_async16z(dst + q * 16, (o >= 0) ? (src + o) : src, (o >= 0) ? 16 : 0);
            }
        }
        if (tid < 144)
            cp_async16(dst + (PATCH + wdst) * 4, wtc + (size_t)ic0 * 9 * OCP + woffc);
    };

    ull acc[4][4];                            // [oc pair][px]
#pragma unroll
    for (int o = 0; o < 4; ++o)
#pragma unroll
        for (int p = 0; p < 4; ++p) acc[o][p] = 0ull;

    issue(0); cp_commit();
    issue(1); cp_commit();

    for (int p = 0; p < NP; ++p) {
        cp_wait1();                           // group p complete (this thread)
        __syncthreads();                      // visibility + retire p-1 readers
        if (p + 2 < NP) issue(p + 2);         // buf[(p+2)%3]=buf[(p-1)%3] now free
        cp_commit();                          // empty tail group keeps wait_group 1 valid

        const float* stage = ring[p % 3];
#pragma unroll
        for (int ics = 0; ics < ICS; ++ics) {
            const float* prow = stage + ics * (PH * RS);
            const float* wrow = stage + PATCH + ics * 144;
#pragma unroll
            for (int ky = 0; ky < 3; ++ky) {
                // activation cols (patch-relative): tx*4+3 .. tx*4+8
                int j0 = (ty + ky) * RS + tx * 4 + 2;
                float2 lo  = *reinterpret_cast<const float2*>(prow + j0);
                float4 mid = *reinterpret_cast<const float4*>(prow + j0 + 2);
                float2 hi  = *reinterpret_cast<const float2*>(prow + j0 + 6);
                ull pv[6];
                pv[0] = pack2(lo.y,  lo.y);
                pv[1] = pack2(mid.x, mid.x); pv[2] = pack2(mid.y, mid.y);
                pv[3] = pack2(mid.z, mid.z); pv[4] = pack2(mid.w, mid.w);
                pv[5] = pack2(hi.x,  hi.x);
#pragma unroll
                for (int kx = 0; kx < 3; ++kx) {
                    const ulonglong2* wr = reinterpret_cast<const ulonglong2*>(
                        wrow + (ky * 3 + kx) * 16 + og * 8);
                    ulonglong2 w0 = wr[0];
                    ulonglong2 w1 = wr[1];
#pragma unroll
                    for (int q = 0; q < 4; ++q) {
                        fma2(acc[0][q], pv[kx + q], w0.x);
                        fma2(acc[1][q], pv[kx + q], w0.y);
                        fma2(acc[2][q], pv[kx + q], w1.x);
                        fma2(acc[3][q], pv[kx + q], w1.y);
                    }
                }
            }
        }
    }

    const int py = by + ty;
    const int px = bx + tx * 4;
#pragma unroll
    for (int op = 0; op < 4; ++op) {
        float2 a[4];
#pragma unroll
        for (int p = 0; p < 4; ++p) a[p] = unpack2(acc[op][p]);
        int oce = oc0 + 2 * op;
#pragma unroll
        for (int lane = 0; lane < 2; ++lane) {
            int oc = oce + lane;
            if (oc >= OC) continue;
            float bv = bias[oc];
            float rr[4];
#pragma unroll
            for (int p = 0; p < 4; ++p) {
                float vv = (lane == 0 ? a[p].x : a[p].y) + bv;
                if (ACT == 1) vv = (vv >= 0.f) ? vv : 0.1f * vv;
                if (ACT == 2) vv = fmaxf(vv, 0.f);
                rr[p] = vv;
            }
            float4 r4; r4.x = rr[0]; r4.y = rr[1]; r4.z = rr[2]; r4.w = rr[3];
            *reinterpret_cast<float4*>(
                &out[((size_t)b * OC + oc) * HW + (size_t)py * WW + px]) = r4;
        }
    }
}

// ---------------------------------------------------------------------------
// Deformable conv core. Thread = 1 pixel, 32 f32x2 oc-pair accumulators.
// Weight slice for tap k+2 streams in via cp.async during compute(k).
// Channel loop software-pipelined: corner LDGs for c+1 issued before
// channel c's fma2 block so L1 latency hides under compute.
// ---------------------------------------------------------------------------
__global__ __launch_bounds__(256, 2)
void dcn_kernel(const float* __restrict__ x, const float* __restrict__ om,
                const float* __restrict__ wt, const float* __restrict__ bias,
                float* __restrict__ out)
{
    __shared__ __align__(16) float ring[3][4096];  // [c][oc] slices

    const int tid  = threadIdx.x;
    const int px0  = tid & 127;
    const int wrow = tid >> 7;
    const int b    = blockIdx.y;
    const int py0  = blockIdx.x * 2 + wrow;
    const int hw   = py0 * WW + px0;

    const float* omb = om + (size_t)b * 27 * HW;
    const float* xb  = x  + (size_t)b * 64 * HW;
    const u32 smbase = (u32)__cvta_generic_to_shared(&ring[0][0]);

    auto issueW = [&](int k) {
        u32 dst = smbase + (u32)(k % 3) * (4096 * 4);
        const float* src = wt + (size_t)k * 4096;
#pragma unroll
        for (int s = 0; s < 4; ++s) {
            int slot = tid + 256 * s;                 // float4 slot
            cp_async16(dst + slot * 16, src + slot * 4);
        }
    };

    ull acc[32];
#pragma unroll
    for (int o = 0; o < 32; ++o) acc[o] = 0ull;

    issueW(0); cp_commit();
    issueW(1); cp_commit();

    for (int k = 0; k < 9; ++k) {
        cp_wait1();
        __syncthreads();
        if (k + 2 < 9) issueW(k + 2);
        cp_commit();

        const float* wk = ring[k % 3];

        float oy = omb[(size_t)k * HW + hw];
        float ox = omb[(size_t)(9 + k) * HW + hw];
        float mr = omb[(size_t)(18 + k) * HW + hw];
        float m  = 1.f / (1.f + __expf(-mr));

        int   ky = k / 3, kx = k - ky * 3;
        float py = (float)(py0 - 1 + ky) + oy;
        float px = (float)(px0 - 1 + kx) + ox;
        float y0f = floorf(py), x0f = floorf(px);
        float ly = py - y0f, lx = px - x0f;
        int y0 = (int)y0f, x0 = (int)x0f;
        int y1 = y0 + 1,   x1 = x0 + 1;

        float vy0 = (y0 >= 0 && y0 <= HH - 1) ? 1.f : 0.f;
        float vy1 = (y1 >= 0 && y1 <= HH - 1) ? 1.f : 0.f;
        float vx0 = (x0 >= 0 && x0 <= WW - 1) ? 1.f : 0.f;
        float vx1 = (x1 >= 0 && x1 <= WW - 1) ? 1.f : 0.f;
        int y0c = min(max(y0, 0), HH - 1), y1c = min(max(y1, 0), HH - 1);
        int x0c = min(max(x0, 0), WW - 1), x1c = min(max(x1, 0), WW - 1);

        float w00 = (1.f - ly) * (1.f - lx) * m * vy0 * vx0;
        float w01 = (1.f - ly) * lx         * m * vy0 * vx1;
        float w10 = ly         * (1.f - lx) * m * vy1 * vx0;
        float w11 = ly         * lx         * m * vy1 * vx1;

        int i00 = y0c * WW + x0c, i01 = y0c * WW + x1c;
        int i10 = y1c * WW + x0c, i11 = y1c * WW + x1c;

        // software pipeline: corners for channel c+1 load during c's fma2s
        const float* xc = xb;
        float n00 = xc[i00], n01 = xc[i01], n10 = xc[i10], n11 = xc[i11];
#pragma unroll 2
        for (int c = 0; c < 64; ++c) {
            float c00 = n00, c01 = n01, c10 = n10, c11 = n11;
            const float* xn = xc + HW;
            if (c < 63) {
                n00 = xn[i00]; n01 = xn[i01]; n10 = xn[i10]; n11 = xn[i11];
            }
            float s = w00 * c00;
            s = fmaf(w01, c01, s);
            s = fmaf(w10, c10, s);
            s = fmaf(w11, c11, s);
            ull ss = pack2(s, s);
            const ulonglong2* wr = reinterpret_cast<const ulonglong2*>(&wk[c * 64]);
#pragma unroll
            for (int j = 0; j < 16; ++j) {
                ulonglong2 q = wr[j];
                fma2(acc[2 * j],     ss, q.x);
                fma2(acc[2 * j + 1], ss, q.y);
            }
            xc = xn;
        }
    }

#pragma unroll
    for (int j = 0; j < 32; ++j) {
        float2 a = unpack2(acc[j]);
        int oc = 2 * j;
        out[((size_t)b * 64 + oc)     * HW + hw] = a.x + bias[oc];
        out[((size_t)b * 64 + oc + 1) * HW + hw] = a.y + bias[oc + 1];
    }
}

// ---------------------------------------------------------------------------
extern "C" void kernel_launch(void* const* d_in, const int* in_sizes, int n_in,
                              void* d_out, int out_size)
{
    const float* x        = (const float*)d_in[0];
    const float* x_neigh  = (const float*)d_in[1];
    const float* offset_t = (const float*)d_in[2];
    const float* w_off1   = (const float*)d_in[3];
    const float* b_off1   = (const float*)d_in[4];
    const float* w_off2   = (const float*)d_in[5];
    const float* b_off2   = (const float*)d_in[6];
    const float* w_off3   = (const float*)d_in[7];
    const float* b_off3   = (const float*)d_in[8];
    const float* w_om     = (const float*)d_in[9];
    const float* b_om     = (const float*)d_in[10];
    const float* w_dcn    = (const float*)d_in[11];
    const float* b_dcn    = (const float*)d_in[12];
    const float* w_outw   = (const float*)d_in[13];
    const float* b_outw   = (const float*)d_in[14];

    float* out        = (float*)d_out;
    float* out_align  = out;                              // (4,64,128,128)
    float* out_offset = out + (size_t)BB * 64 * HW;       // (4,64,128,128)

    float *p1, *p2, *pom, *pal, *pwt;
    float *pw1, *pw2, *pw3, *pwm, *pwo;
    cudaGetSymbolAddress((void**)&p1,  g_buf1);
    cudaGetSymbolAddress((void**)&p2,  g_buf2);
    cudaGetSymbolAddress((void**)&pom, g_om);
    cudaGetSymbolAddress((void**)&pal, g_align);
    cudaGetSymbolAddress((void**)&pwt, g_wt);
    cudaGetSymbolAddress((void**)&pw1, g_wt1);
    cudaGetSymbolAddress((void**)&pw2, g_wt2);
    cudaGetSymbolAddress((void**)&pw3, g_wt3);
    cudaGetSymbolAddress((void**)&pwm, g_wtm);
    cudaGetSymbolAddress((void**)&pwo, g_wto);

    dim3 blk(256);
    dim3 g64(2, 16, BB * 4);  // 64 oc -> 4 oc-blocks of 16; 512 blocks
    dim3 gom(2, 16, BB * 2);  // 27 oc -> 2 oc-blocks of 16 (guarded); 256 blocks

    // single merged one-off transpose launch
    transpose_all_kernel<<<(NT + 255) / 256, blk>>>(
        w_off1, w_off2, w_off3, w_om, w_outw, w_dcn,
        pw1, pw2, pw3, pwm, pwo, pwt);

    conv3x3_kernel<128, 1, 64><<<g64, blk>>>(x, x_neigh, pw1, b_off1, p1, 4, 64);
    conv3x3_kernel<128, 1, 64><<<g64, blk>>>(p1, offset_t, pw2, b_off2, p2, 4, 64);
    conv3x3_kernel<64, 1, 64><<<g64, blk>>>(p2, nullptr, pw3, b_off3, out_offset, 4, 64);
    conv3x3_kernel<64, 0, 32><<<gom, blk>>>(out_offset, nullptr, pwm, b_om, pom, 2, 27);

    dim3 gd(64, BB);
    dcn_kernel<<<gd, blk>>>(x, pom, pwt, b_dcn, pal);

    conv3x3_kernel<64, 2, 64><<<g64, blk>>>(pal, nullptr, pwo, b_outw, out_align, 4, 64);
}